// round 15
// baseline (speedup 1.0000x reference)
#include <cuda_runtime.h>
#include <cuda_fp16.h>
#include <math.h>
#include <stdint.h>

#define T_TOK 4096
#define HDIM 1024
#define FDIM 512
#define NEXP 8
#define MAXP 4096
#define NTILE 72
#define N_GU (NTILE * 8)
#define N_ITEMS (N_GU + NTILE * 8)
#define NCTA 296

// ---------------- device scratch ----------------
__device__ int    g_cnt[NEXP];
__device__ int    g_tok[NEXP * MAXP];
__device__ float  g_wt [NEXP * MAXP];
__device__ int    g_pair[T_TOK * 2];
__device__ __half g_xh  [T_TOK * HDIM];
__device__ __half g_acth[T_TOK * 2 * FDIM];
__device__ float  g_dout[T_TOK * 2 * HDIM];
__device__ int    g_gudone[NTILE];
__device__ int    g_work;
__device__ int    g_fin;
__device__ int    g_cfin;

#define MMA16(c, a0, a1, a2, a3, b0, b1) \
    asm volatile("mma.sync.aligned.m16n8k16.row.col.f32.f16.f16.f32 " \
        "{%0,%1,%2,%3},{%4,%5,%6,%7},{%8,%9},{%0,%1,%2,%3};" \
        : "+f"((c)[0]), "+f"((c)[1]), "+f"((c)[2]), "+f"((c)[3]) \
        : "r"(a0), "r"(a1), "r"(a2), "r"(a3), "r"(b0), "r"(b1))

__device__ __forceinline__ uint32_t h2u(__half2 h) {
    uint32_t u; asm("mov.b32 %0, %1;" : "=r"(u) : "r"(*(uint32_t*)&h)); return u;
}

// smem (uint2 units): A 8q x 132m, B 8q x 132n, per buffer 2112 uint2 (R7 layout)
#define QST 132
#define BUF2 2112
#define AOFF(b) ((b) * BUF2)
#define BOFF(b) ((b) * BUF2 + 8 * QST)
#define META2 (2 * BUF2)
#define GEMM_SMEM (2 * BUF2 * 8 + 1024)

__device__ __forceinline__ bool tile_map(int tile, int& e, int& m0, int& gbase, int& cnt) {
    int acc = 0, off = 0;
#pragma unroll
    for (int i = 0; i < NEXP; i++) {
        int c = g_cnt[i];
        int nt = (c + 127) >> 7;
        if (tile < acc + nt) { e = i; m0 = (tile - acc) << 7; gbase = off; cnt = c; return true; }
        acc += nt; off += c;
    }
    return false;
}

// ---------------- router v3 (R14, passing) ----------------
__global__ __launch_bounds__(512) void router_kernel(
    const float* __restrict__ x, const float* __restrict__ Wr)
{
    __shared__ float s_wr[NEXP * 1032];
    int tid = threadIdx.x;
#pragma unroll
    for (int j = 0; j < 4; j++) {
        int idx = (j * 512 + tid) * 4;
        float4 v = *(const float4*)(Wr + idx);
        int h = idx >> 3, e0 = idx & 7;
        s_wr[(e0 + 0) * 1032 + h] = v.x;
        s_wr[(e0 + 1) * 1032 + h] = v.y;
        s_wr[(e0 + 2) * 1032 + h] = v.z;
        s_wr[(e0 + 3) * 1032 + h] = v.w;
    }
    __syncthreads();

    int lane = tid & 31, wid = tid >> 5;
    for (int tt = 0; tt < 2; tt++) {
        int t = blockIdx.x * 32 + wid * 2 + tt;
        const float4* xr4 = (const float4*)(x + (size_t)t * HDIM);
        float acc[NEXP];
#pragma unroll
        for (int e = 0; e < NEXP; e++) acc[e] = 0.0f;
#pragma unroll
        for (int j = 0; j < 8; j++) {
            int hq = j * 32 + lane;
            float4 xv = xr4[hq];
            __half2 lo = __floats2half2_rn(xv.x, xv.y);
            __half2 hi = __floats2half2_rn(xv.z, xv.w);
            *(uint2*)(g_xh + (size_t)t * HDIM + hq * 4) = make_uint2(h2u(lo), h2u(hi));
#pragma unroll
            for (int e = 0; e < NEXP; e++) {
                float4 wv = *(const float4*)(s_wr + e * 1032 + hq * 4);
                acc[e] = fmaf(xv.x, wv.x, fmaf(xv.y, wv.y,
                         fmaf(xv.z, wv.z, fmaf(xv.w, wv.w, acc[e]))));
            }
        }
#pragma unroll
        for (int e = 0; e < NEXP; e++)
#pragma unroll
            for (int o = 16; o > 0; o >>= 1)
                acc[e] += __shfl_xor_sync(0xFFFFFFFFu, acc[e], o);
        if (lane == 0) {
            float m = acc[0];
#pragma unroll
            for (int e = 1; e < NEXP; e++) m = fmaxf(m, acc[e]);
            float p[NEXP];
#pragma unroll
            for (int e = 0; e < NEXP; e++) p[e] = expf(acc[e] - m);
            int i0 = 0;
#pragma unroll
            for (int e = 1; e < NEXP; e++) if (p[e] > p[i0]) i0 = e;
            int i1 = (i0 == 0) ? 1 : 0;
#pragma unroll
            for (int e = 0; e < NEXP; e++) if (e != i0 && p[e] > p[i1]) i1 = e;
            float s = p[i0] + p[i1];
            int p0 = atomicAdd(&g_cnt[i0], 1);
            g_tok[i0 * MAXP + p0] = t; g_wt[i0 * MAXP + p0] = p[i0] / s;
            g_pair[t * 2 + 0] = (i0 << 12) | p0;
            int p1 = atomicAdd(&g_cnt[i1], 1);
            g_tok[i1 * MAXP + p1] = t; g_wt[i1 * MAXP + p1] = p[i1] / s;
            g_pair[t * 2 + 1] = (i1 << 12) | p1;
        }
    }
}

// ---------------- gateup body (R7 core) ----------------
__device__ void gateup_body(uint2* sm2, int tile, int f0,
                            const float* __restrict__ Wg,
                            const float* __restrict__ Wu)
{
    int e, m0, gbase, cnt;
    if (!tile_map(tile, e, m0, gbase, cnt)) return;

    int tid = threadIdx.x, lane = tid & 31, wid = tid >> 5;
    int wmi = wid >> 2, wni = wid & 3;
    int lr = lane >> 2, l3 = lane & 3;

    int*   stok = (int*)(sm2 + META2);
    float* swt  = (float*)(sm2 + META2 + 64);
    if (tid < 128) {
        int r = m0 + tid, rc = min(r, cnt - 1);
        stok[tid] = g_tok[e * MAXP + rc];
        swt[tid]  = (r < cnt) ? g_wt[e * MAXP + rc] : 0.0f;
    }
    __syncthreads();

    int am = tid >> 1, kh = (tid & 1) * 16;
    const __half* arow = g_xh + (size_t)stok[am] * HDIM + kh;
    int aqb = (tid & 1) * 4;
    int bp = (wid & 3) + 8 * (wid >> 2);
    int n4 = lane * 4;
    int bmat = (n4 >> 4) & 1;
    int bf = ((n4 >> 5) << 4) + (((n4 >> 3) & 1) << 3) + (n4 & 7);
    const float* wsel = (bmat ? Wu : Wg) + (size_t)e * HDIM * FDIM + f0 + bf;

    uint4 au0, au1;
    float4 bv0, bv1, bv2, bv3;
    auto LOADG = [&](int s) {
        int kb = s * 32;
        const uint4* ap = (const uint4*)(arow + kb);
        au0 = ap[0]; au1 = ap[1];
        const float* bp0 = wsel + (size_t)(kb + 2 * bp) * FDIM;
        bv0 = *(const float4*)bp0;
        bv1 = *(const float4*)(bp0 + FDIM);
        bv2 = *(const float4*)(bp0 + 8 * FDIM);
        bv3 = *(const float4*)(bp0 + 9 * FDIM);
    };
    auto STORES = [&](int b) {
        uint2* A = sm2 + AOFF(b);
        uint2* B = sm2 + BOFF(b);
        const uint32_t* a0 = (const uint32_t*)&au0;
        const uint32_t* a1 = (const uint32_t*)&au1;
#pragma unroll
        for (int j = 0; j < 4; j++)
            A[(aqb + j) * QST + am] = make_uint2(a0[j], a1[j]);
        const float* v0 = (const float*)&bv0;
        const float* v1 = (const float*)&bv1;
        const float* v2 = (const float*)&bv2;
        const float* v3 = (const float*)&bv3;
#pragma unroll
        for (int j = 0; j < 4; j++) {
            uint32_t lo = h2u(__floats2half2_rn(v0[j], v1[j]));
            uint32_t hi = h2u(__floats2half2_rn(v2[j], v3[j]));
            B[wid * QST + n4 + j] = make_uint2(lo, hi);
        }
    };

    float c[4][4][4];
#pragma unroll
    for (int a = 0; a < 4; a++)
#pragma unroll
        for (int b = 0; b < 4; b++)
#pragma unroll
            for (int k = 0; k < 4; k++) c[a][b][k] = 0.0f;

    LOADG(0); STORES(0);
    const int NS = HDIM / 32;
    for (int s = 0; s < NS; s++) {
        __syncthreads();
        if (s + 1 < NS) LOADG(s + 1);
        uint2* A = sm2 + AOFF(s & 1);
        uint2* B = sm2 + BOFF(s & 1);
#pragma unroll
        for (int kk = 0; kk < 2; kk++) {
            int q = kk * 4 + l3;
            uint2 af[4], ah[4];
#pragma unroll
            for (int mt = 0; mt < 4; mt++) {
                int m = wmi * 64 + mt * 16 + lr;
                af[mt] = A[q * QST + m];
                ah[mt] = A[q * QST + m + 8];
            }
#pragma unroll
            for (int nt = 0; nt < 4; nt++) {
                uint2 b = B[q * QST + wni * 32 + nt * 8 + lr];
#pragma unroll
                for (int mt = 0; mt < 4; mt++)
                    MMA16(c[mt][nt], af[mt].x, ah[mt].x, af[mt].y, ah[mt].y, b.x, b.y);
            }
        }
        if (s + 1 < NS) STORES((s + 1) & 1);
    }

#pragma unroll
    for (int mt = 0; mt < 4; mt++)
#pragma unroll
        for (int rr = 0; rr < 2; rr++) {
            int row = wmi * 64 + mt * 16 + lr + rr * 8;
            if (m0 + row < cnt) {
                float w = swt[row];
                __half* dst = g_acth + (size_t)(gbase + m0 + row) * FDIM + f0 + wni * 16 + 2 * l3;
#pragma unroll
                for (int ntl = 0; ntl < 2; ntl++) {
                    float gv0 = c[mt][ntl][rr * 2],     gv1 = c[mt][ntl][rr * 2 + 1];
                    float uv0 = c[mt][ntl + 2][rr * 2], uv1 = c[mt][ntl + 2][rr * 2 + 1];
                    float o0 = w * (gv0 / (1.0f + expf(-gv0))) * uv0;
                    float o1 = w * (gv1 / (1.0f + expf(-gv1))) * uv1;
                    *(__half2*)(dst + ntl * 8) = __floats2half2_rn(o0, o1);
                }
            }
        }

    // release: g_acth writes visible, then signal
    __threadfence();
    __syncthreads();
    if (tid == 0) atomicAdd(&g_gudone[tile], 1);
}

// ---------------- down body (R7 core) ----------------
__device__ void down_body(uint2* sm2, int tile, int h0,
                          const float* __restrict__ Wd)
{
    int e, m0, gbase, cnt;
    if (!tile_map(tile, e, m0, gbase, cnt)) return;

    int tid = threadIdx.x, lane = tid & 31, wid = tid >> 5;
    int wmi = wid >> 2, wni = wid & 3;
    int lr = lane >> 2, l3 = lane & 3;

    // acquire: wait for all 8 gateup f-blocks of this row-tile
    if (tid == 0) {
        volatile int* done = g_gudone + tile;
        while (*done < 8) __nanosleep(128);
    }
    __syncthreads();
    __threadfence();

    int am = tid >> 1, kh = (tid & 1) * 16;
    const __half* arow = g_acth + (size_t)(gbase + min(m0 + am, cnt - 1)) * FDIM + kh;
    int aqb = (tid & 1) * 4;
    int bp = (wid & 3) + 8 * (wid >> 2);
    int n4 = lane * 4;
    const float* wsel = Wd + (size_t)e * FDIM * HDIM + h0 + n4;

    uint4 au0, au1;
    float4 bv0, bv1, bv2, bv3;
    auto LOADG = [&](int s) {
        int kb = s * 32;
        const uint4* ap = (const uint4*)(arow + kb);
        au0 = ap[0]; au1 = ap[1];
        const float* bp0 = wsel + (size_t)(kb + 2 * bp) * HDIM;
        bv0 = *(const float4*)bp0;
        bv1 = *(const float4*)(bp0 + HDIM);
        bv2 = *(const float4*)(bp0 + 8 * HDIM);
        bv3 = *(const float4*)(bp0 + 9 * HDIM);
    };
    auto STORES = [&](int b) {
        uint2* A = sm2 + AOFF(b);
        uint2* B = sm2 + BOFF(b);
        const uint32_t* a0 = (const uint32_t*)&au0;
        const uint32_t* a1 = (const uint32_t*)&au1;
#pragma unroll
        for (int j = 0; j < 4; j++)
            A[(aqb + j) * QST + am] = make_uint2(a0[j], a1[j]);
        const float* v0 = (const float*)&bv0;
        const float* v1 = (const float*)&bv1;
        const float* v2 = (const float*)&bv2;
        const float* v3 = (const float*)&bv3;
#pragma unroll
        for (int j = 0; j < 4; j++) {
            uint32_t lo = h2u(__floats2half2_rn(v0[j], v1[j]));
            uint32_t hi = h2u(__floats2half2_rn(v2[j], v3[j]));
            B[wid * QST + n4 + j] = make_uint2(lo, hi);
        }
    };

    float c[4][4][4];
#pragma unroll
    for (int a = 0; a < 4; a++)
#pragma unroll
        for (int b = 0; b < 4; b++)
#pragma unroll
            for (int k = 0; k < 4; k++) c[a][b][k] = 0.0f;

    LOADG(0); STORES(0);
    const int NS = FDIM / 32;
    for (int s = 0; s < NS; s++) {
        __syncthreads();
        if (s + 1 < NS) LOADG(s + 1);
        uint2* A = sm2 + AOFF(s & 1);
        uint2* B = sm2 + BOFF(s & 1);
#pragma unroll
        for (int kk = 0; kk < 2; kk++) {
            int q = kk * 4 + l3;
            uint2 af[4], ah[4];
#pragma unroll
            for (int mt = 0; mt < 4; mt++) {
                int m = wmi * 64 + mt * 16 + lr;
                af[mt] = A[q * QST + m];
                ah[mt] = A[q * QST + m + 8];
            }
#pragma unroll
            for (int nt = 0; nt < 4; nt++) {
                uint2 b = B[q * QST + wni * 32 + nt * 8 + lr];
#pragma unroll
                for (int mt = 0; mt < 4; mt++)
                    MMA16(c[mt][nt], af[mt].x, ah[mt].x, af[mt].y, ah[mt].y, b.x, b.y);
            }
        }
        if (s + 1 < NS) STORES((s + 1) & 1);
    }

#pragma unroll
    for (int mt = 0; mt < 4; mt++)
#pragma unroll
        for (int rr = 0; rr < 2; rr++) {
            int row = wmi * 64 + mt * 16 + lr + rr * 8;
            if (m0 + row < cnt) {
                float* dst = g_dout + (size_t)(gbase + m0 + row) * HDIM + h0 + wni * 32 + 2 * l3;
#pragma unroll
                for (int nt = 0; nt < 4; nt++)
                    *(float2*)(dst + nt * 8) =
                        make_float2(c[mt][nt][rr * 2], c[mt][nt][rr * 2 + 1]);
            }
        }
}

// ---------------- persistent fused GEMM scheduler ----------------
__global__ __launch_bounds__(256, 2) void moe_fused(
    const float* __restrict__ Wg, const float* __restrict__ Wu,
    const float* __restrict__ Wd)
{
    extern __shared__ uint2 sm2[];
    __shared__ int s_item;
    while (true) {
        if (threadIdx.x == 0) s_item = atomicAdd(&g_work, 1);
        __syncthreads();
        int item = s_item;
        if (item >= N_ITEMS) break;
        if (item < N_GU)
            gateup_body(sm2, item >> 3, (item & 7) * 64, Wg, Wu);
        else {
            int d = item - N_GU;
            down_body(sm2, d >> 3, (d & 7) * 128, Wd);
        }
        __syncthreads();
    }
    // last CTA resets scheduler state for the next replay
    if (threadIdx.x == 0) {
        __threadfence();
        int d = atomicAdd(&g_fin, 1);
        if (d == NCTA - 1) {
            g_work = 0; g_fin = 0;
#pragma unroll
            for (int i = 0; i < NTILE; i++) g_gudone[i] = 0;
            __threadfence();
        }
    }
}

// ---------------- combine (fp32, inline offsets) + g_cnt reset ----------------
__global__ __launch_bounds__(256) void combine_kernel(float* __restrict__ out)
{
    int idx = blockIdx.x * blockDim.x + threadIdx.x;
    int t = idx >> 8;
    int hq = (idx & 255) * 4;
    int v0 = g_pair[t * 2 + 0], v1 = g_pair[t * 2 + 1];
    int e0 = v0 >> 12, e1 = v1 >> 12;
    int off0 = 0, off1 = 0;
#pragma unroll
    for (int i = 0; i < NEXP; i++) {
        int ci = g_cnt[i];
        if (i < e0) off0 += ci;
        if (i < e1) off1 += ci;
    }
    int gi0 = off0 + (v0 & (MAXP - 1));
    int gi1 = off1 + (v1 & (MAXP - 1));
    float4 a = *(const float4*)(g_dout + (size_t)gi0 * HDIM + hq);
    float4 b = *(const float4*)(g_dout + (size_t)gi1 * HDIM + hq);
    float4 o = {a.x + b.x, a.y + b.y, a.z + b.z, a.w + b.w};
    *(float4*)(out + (size_t)t * HDIM + hq) = o;

    // last block re-zeroes g_cnt for the next replay
    __syncthreads();
    if (threadIdx.x == 0) {
        __threadfence();
        int d = atomicAdd(&g_cfin, 1);
        if (d == (int)gridDim.x - 1) {
            g_cfin = 0;
#pragma unroll
            for (int i = 0; i < NEXP; i++) g_cnt[i] = 0;
            __threadfence();
        }
    }
}

// ---------------- launch ----------------
extern "C" void kernel_launch(void* const* d_in, const int* in_sizes, int n_in,
                              void* d_out, int out_size)
{
    const float* x  = (const float*)d_in[0];
    const float* Wr = (const float*)d_in[1];
    const float* Wg = (const float*)d_in[2];
    const float* Wu = (const float*)d_in[3];
    const float* Wd = (const float*)d_in[4];
    float* out = (float*)d_out;

    cudaFuncSetAttribute(moe_fused, cudaFuncAttributeMaxDynamicSharedMemorySize, GEMM_SMEM);

    router_kernel<<<T_TOK / 32, 512>>>(x, Wr);
    moe_fused<<<NCTA, 256, GEMM_SMEM>>>(Wg, Wu, Wd);
    combine_kernel<<<(T_TOK * HDIM / 4) / 256, 256>>>(out);
}

// round 16
// speedup vs baseline: 1.0238x; 1.0238x over previous
#include <cuda_runtime.h>
#include <cuda_fp16.h>
#include <math.h>
#include <stdint.h>

#define T_TOK 4096
#define HDIM 1024
#define FDIM 512
#define NEXP 8
#define MAXP 4096

// ---------------- device scratch ----------------
__device__ int    g_cnt[NEXP];          // zero-initialized at load; reset by combine
__device__ int    g_tok[NEXP * MAXP];
__device__ float  g_wt [NEXP * MAXP];
__device__ int    g_pair[T_TOK * 2];
__device__ __half g_xh  [T_TOK * HDIM];
__device__ __half g_acth[T_TOK * 2 * FDIM];
__device__ float  g_dout[T_TOK * 2 * HDIM];
__device__ int    g_cfin;

#define MMA16(c, a0, a1, a2, a3, b0, b1) \
    asm volatile("mma.sync.aligned.m16n8k16.row.col.f32.f16.f16.f32 " \
        "{%0,%1,%2,%3},{%4,%5,%6,%7},{%8,%9},{%0,%1,%2,%3};" \
        : "+f"((c)[0]), "+f"((c)[1]), "+f"((c)[2]), "+f"((c)[3]) \
        : "r"(a0), "r"(a1), "r"(a2), "r"(a3), "r"(b0), "r"(b1))

__device__ __forceinline__ uint32_t h2u(__half2 h) {
    uint32_t u; asm("mov.b32 %0, %1;" : "=r"(u) : "r"(*(uint32_t*)&h)); return u;
}

// smem (uint2 units): A 8q x 132m, B 8q x 132n, per buffer 2112 uint2 (R7 layout)
#define QST 132
#define BUF2 2112
#define AOFF(b) ((b) * BUF2)
#define BOFF(b) ((b) * BUF2 + 8 * QST)
#define META2 (2 * BUF2)
#define GEMM_SMEM (2 * BUF2 * 8 + 1024)

// map flat tile -> (expert, m0, gbase, cnt); tiles are 128 rows
__device__ __forceinline__ bool tile_map(int tile, int& e, int& m0, int& gbase, int& cnt) {
    int acc = 0, off = 0;
#pragma unroll
    for (int i = 0; i < NEXP; i++) {
        int c = g_cnt[i];
        int nt = (c + 127) >> 7;
        if (tile < acc + nt) { e = i; m0 = (tile - acc) << 7; gbase = off; cnt = c; return true; }
        acc += nt; off += c;
    }
    return false;
}

// ---------------- router v4: 4 tokens per warp, Wr reuse in registers ----------------
__global__ __launch_bounds__(128) void router_kernel(
    const float* __restrict__ x, const float* __restrict__ Wr)
{
    int lane = threadIdx.x & 31, wid = threadIdx.x >> 5;
    int t0 = blockIdx.x * 16 + wid * 4;
    const float* xr0 = x + (size_t)(t0 + 0) * HDIM;
    const float* xr1 = x + (size_t)(t0 + 1) * HDIM;
    const float* xr2 = x + (size_t)(t0 + 2) * HDIM;
    const float* xr3 = x + (size_t)(t0 + 3) * HDIM;

    float acc[4][NEXP];
#pragma unroll
    for (int i = 0; i < 4; i++)
#pragma unroll
        for (int e = 0; e < NEXP; e++) acc[i][e] = 0.0f;

    for (int h = lane; h < HDIM; h += 32) {
        const float4* wr4 = (const float4*)(Wr + (size_t)h * NEXP);
        float4 w0 = wr4[0], w1 = wr4[1];
        float xv0 = xr0[h], xv1 = xr1[h], xv2 = xr2[h], xv3 = xr3[h];
        g_xh[(size_t)(t0 + 0) * HDIM + h] = __float2half_rn(xv0);
        g_xh[(size_t)(t0 + 1) * HDIM + h] = __float2half_rn(xv1);
        g_xh[(size_t)(t0 + 2) * HDIM + h] = __float2half_rn(xv2);
        g_xh[(size_t)(t0 + 3) * HDIM + h] = __float2half_rn(xv3);
        float xs[4] = {xv0, xv1, xv2, xv3};
#pragma unroll
        for (int i = 0; i < 4; i++) {
            acc[i][0] = fmaf(xs[i], w0.x, acc[i][0]);
            acc[i][1] = fmaf(xs[i], w0.y, acc[i][1]);
            acc[i][2] = fmaf(xs[i], w0.z, acc[i][2]);
            acc[i][3] = fmaf(xs[i], w0.w, acc[i][3]);
            acc[i][4] = fmaf(xs[i], w1.x, acc[i][4]);
            acc[i][5] = fmaf(xs[i], w1.y, acc[i][5]);
            acc[i][6] = fmaf(xs[i], w1.z, acc[i][6]);
            acc[i][7] = fmaf(xs[i], w1.w, acc[i][7]);
        }
    }
#pragma unroll
    for (int i = 0; i < 4; i++)
#pragma unroll
        for (int e = 0; e < NEXP; e++)
#pragma unroll
            for (int o = 16; o > 0; o >>= 1)
                acc[i][e] += __shfl_xor_sync(0xFFFFFFFFu, acc[i][e], o);

    if (lane == 0) {
#pragma unroll
        for (int i = 0; i < 4; i++) {
            int t = t0 + i;
            float m = acc[i][0];
#pragma unroll
            for (int e = 1; e < NEXP; e++) m = fmaxf(m, acc[i][e]);
            float p[NEXP];
#pragma unroll
            for (int e = 0; e < NEXP; e++) p[e] = expf(acc[i][e] - m);
            int i0 = 0;
#pragma unroll
            for (int e = 1; e < NEXP; e++) if (p[e] > p[i0]) i0 = e;
            int i1 = (i0 == 0) ? 1 : 0;
#pragma unroll
            for (int e = 0; e < NEXP; e++) if (e != i0 && p[e] > p[i1]) i1 = e;
            float s = p[i0] + p[i1];
            int p0 = atomicAdd(&g_cnt[i0], 1);
            g_tok[i0 * MAXP + p0] = t; g_wt[i0 * MAXP + p0] = p[i0] / s;
            g_pair[t * 2 + 0] = (i0 << 12) | p0;
            int p1 = atomicAdd(&g_cnt[i1], 1);
            g_tok[i1 * MAXP + p1] = t; g_wt[i1 * MAXP + p1] = p[i1] / s;
            g_pair[t * 2 + 1] = (i1 << 12) | p1;
        }
    }
}

// =====================================================================
// gate+up fp16 GEMM + SwiGLU (R7 core). Block 128m x 128n', BK=32,
// 256 threads, 8 warps (2m x 4n), warp 64x32, 2 CTAs/SM.
// =====================================================================
__global__ __launch_bounds__(256, 2) void mg_gateup(
    const float* __restrict__ Wg,
    const float* __restrict__ Wu)
{
    extern __shared__ uint2 sm2[];
    int e, m0, gbase, cnt;
    if (!tile_map(blockIdx.x, e, m0, gbase, cnt)) return;
    int f0 = blockIdx.y * 64;

    int tid = threadIdx.x, lane = tid & 31, wid = tid >> 5;
    int wmi = wid >> 2, wni = wid & 3;
    int lr = lane >> 2, l3 = lane & 3;

    int*   stok = (int*)(sm2 + META2);
    float* swt  = (float*)(sm2 + META2 + 64);
    if (tid < 128) {
        int r = m0 + tid, rc = min(r, cnt - 1);
        stok[tid] = g_tok[e * MAXP + rc];
        swt[tid]  = (r < cnt) ? g_wt[e * MAXP + rc] : 0.0f;
    }
    __syncthreads();

    int am = tid >> 1, kh = (tid & 1) * 16;
    const __half* arow = g_xh + (size_t)stok[am] * HDIM + kh;
    int aqb = (tid & 1) * 4;
    int bp = (wid & 3) + 8 * (wid >> 2);
    int n4 = lane * 4;
    int bmat = (n4 >> 4) & 1;
    int bf = ((n4 >> 5) << 4) + (((n4 >> 3) & 1) << 3) + (n4 & 7);
    const float* wsel = (bmat ? Wu : Wg) + (size_t)e * HDIM * FDIM + f0 + bf;

    uint4 au0, au1;
    float4 bv0, bv1, bv2, bv3;
    auto LOADG = [&](int s) {
        int kb = s * 32;
        const uint4* ap = (const uint4*)(arow + kb);
        au0 = ap[0]; au1 = ap[1];
        const float* bp0 = wsel + (size_t)(kb + 2 * bp) * FDIM;
        bv0 = *(const float4*)bp0;
        bv1 = *(const float4*)(bp0 + FDIM);
        bv2 = *(const float4*)(bp0 + 8 * FDIM);
        bv3 = *(const float4*)(bp0 + 9 * FDIM);
    };
    auto STORES = [&](int b) {
        uint2* A = sm2 + AOFF(b);
        uint2* B = sm2 + BOFF(b);
        const uint32_t* a0 = (const uint32_t*)&au0;
        const uint32_t* a1 = (const uint32_t*)&au1;
#pragma unroll
        for (int j = 0; j < 4; j++)
            A[(aqb + j) * QST + am] = make_uint2(a0[j], a1[j]);
        const float* v0 = (const float*)&bv0;
        const float* v1 = (const float*)&bv1;
        const float* v2 = (const float*)&bv2;
        const float* v3 = (const float*)&bv3;
#pragma unroll
        for (int j = 0; j < 4; j++) {
            uint32_t lo = h2u(__floats2half2_rn(v0[j], v1[j]));
            uint32_t hi = h2u(__floats2half2_rn(v2[j], v3[j]));
            B[wid * QST + n4 + j] = make_uint2(lo, hi);
        }
    };

    float c[4][4][4];
#pragma unroll
    for (int a = 0; a < 4; a++)
#pragma unroll
        for (int b = 0; b < 4; b++)
#pragma unroll
            for (int k = 0; k < 4; k++) c[a][b][k] = 0.0f;

    LOADG(0); STORES(0);
    const int NS = HDIM / 32;
    for (int s = 0; s < NS; s++) {
        __syncthreads();
        if (s + 1 < NS) LOADG(s + 1);
        uint2* A = sm2 + AOFF(s & 1);
        uint2* B = sm2 + BOFF(s & 1);
#pragma unroll
        for (int kk = 0; kk < 2; kk++) {
            int q = kk * 4 + l3;
            uint2 af[4], ah[4];
#pragma unroll
            for (int mt = 0; mt < 4; mt++) {
                int m = wmi * 64 + mt * 16 + lr;
                af[mt] = A[q * QST + m];
                ah[mt] = A[q * QST + m + 8];
            }
#pragma unroll
            for (int nt = 0; nt < 4; nt++) {
                uint2 b = B[q * QST + wni * 32 + nt * 8 + lr];
#pragma unroll
                for (int mt = 0; mt < 4; mt++)
                    MMA16(c[mt][nt], af[mt].x, ah[mt].x, af[mt].y, ah[mt].y, b.x, b.y);
            }
        }
        if (s + 1 < NS) STORES((s + 1) & 1);
    }

#pragma unroll
    for (int mt = 0; mt < 4; mt++)
#pragma unroll
        for (int rr = 0; rr < 2; rr++) {
            int row = wmi * 64 + mt * 16 + lr + rr * 8;
            if (m0 + row < cnt) {
                float w = swt[row];
                __half* dst = g_acth + (size_t)(gbase + m0 + row) * FDIM + f0 + wni * 16 + 2 * l3;
#pragma unroll
                for (int ntl = 0; ntl < 2; ntl++) {
                    float gv0 = c[mt][ntl][rr * 2],     gv1 = c[mt][ntl][rr * 2 + 1];
                    float uv0 = c[mt][ntl + 2][rr * 2], uv1 = c[mt][ntl + 2][rr * 2 + 1];
                    float o0 = w * (gv0 / (1.0f + expf(-gv0))) * uv0;
                    float o1 = w * (gv1 / (1.0f + expf(-gv1))) * uv1;
                    *(__half2*)(dst + ntl * 8) = __floats2half2_rn(o0, o1);
                }
            }
        }
}

// =====================================================================
// down fp16 GEMM (R7 core). Block 128m x 128h, BK=32, warp 64x32.
// =====================================================================
__global__ __launch_bounds__(256, 2) void mg_down(const float* __restrict__ Wd)
{
    extern __shared__ uint2 sm2[];
    int e, m0, gbase, cnt;
    if (!tile_map(blockIdx.x, e, m0, gbase, cnt)) return;
    int h0 = blockIdx.y * 128;

    int tid = threadIdx.x, lane = tid & 31, wid = tid >> 5;
    int wmi = wid >> 2, wni = wid & 3;
    int lr = lane >> 2, l3 = lane & 3;

    int am = tid >> 1, kh = (tid & 1) * 16;
    const __half* arow = g_acth + (size_t)(gbase + min(m0 + am, cnt - 1)) * FDIM + kh;
    int aqb = (tid & 1) * 4;
    int bp = (wid & 3) + 8 * (wid >> 2);
    int n4 = lane * 4;
    const float* wsel = Wd + (size_t)e * FDIM * HDIM + h0 + n4;

    uint4 au0, au1;
    float4 bv0, bv1, bv2, bv3;
    auto LOADG = [&](int s) {
        int kb = s * 32;
        const uint4* ap = (const uint4*)(arow + kb);
        au0 = ap[0]; au1 = ap[1];
        const float* bp0 = wsel + (size_t)(kb + 2 * bp) * HDIM;
        bv0 = *(const float4*)bp0;
        bv1 = *(const float4*)(bp0 + HDIM);
        bv2 = *(const float4*)(bp0 + 8 * HDIM);
        bv3 = *(const float4*)(bp0 + 9 * HDIM);
    };
    auto STORES = [&](int b) {
        uint2* A = sm2 + AOFF(b);
        uint2* B = sm2 + BOFF(b);
        const uint32_t* a0 = (const uint32_t*)&au0;
        const uint32_t* a1 = (const uint32_t*)&au1;
#pragma unroll
        for (int j = 0; j < 4; j++)
            A[(aqb + j) * QST + am] = make_uint2(a0[j], a1[j]);
        const float* v0 = (const float*)&bv0;
        const float* v1 = (const float*)&bv1;
        const float* v2 = (const float*)&bv2;
        const float* v3 = (const float*)&bv3;
#pragma unroll
        for (int j = 0; j < 4; j++) {
            uint32_t lo = h2u(__floats2half2_rn(v0[j], v1[j]));
            uint32_t hi = h2u(__floats2half2_rn(v2[j], v3[j]));
            B[wid * QST + n4 + j] = make_uint2(lo, hi);
        }
    };

    float c[4][4][4];
#pragma unroll
    for (int a = 0; a < 4; a++)
#pragma unroll
        for (int b = 0; b < 4; b++)
#pragma unroll
            for (int k = 0; k < 4; k++) c[a][b][k] = 0.0f;

    LOADG(0); STORES(0);
    const int NS = FDIM / 32;
    for (int s = 0; s < NS; s++) {
        __syncthreads();
        if (s + 1 < NS) LOADG(s + 1);
        uint2* A = sm2 + AOFF(s & 1);
        uint2* B = sm2 + BOFF(s & 1);
#pragma unroll
        for (int kk = 0; kk < 2; kk++) {
            int q = kk * 4 + l3;
            uint2 af[4], ah[4];
#pragma unroll
            for (int mt = 0; mt < 4; mt++) {
                int m = wmi * 64 + mt * 16 + lr;
                af[mt] = A[q * QST + m];
                ah[mt] = A[q * QST + m + 8];
            }
#pragma unroll
            for (int nt = 0; nt < 4; nt++) {
                uint2 b = B[q * QST + wni * 32 + nt * 8 + lr];
#pragma unroll
                for (int mt = 0; mt < 4; mt++)
                    MMA16(c[mt][nt], af[mt].x, ah[mt].x, af[mt].y, ah[mt].y, b.x, b.y);
            }
        }
        if (s + 1 < NS) STORES((s + 1) & 1);
    }

#pragma unroll
    for (int mt = 0; mt < 4; mt++)
#pragma unroll
        for (int rr = 0; rr < 2; rr++) {
            int row = wmi * 64 + mt * 16 + lr + rr * 8;
            if (m0 + row < cnt) {
                float* dst = g_dout + (size_t)(gbase + m0 + row) * HDIM + h0 + wni * 32 + 2 * l3;
#pragma unroll
                for (int nt = 0; nt < 4; nt++)
                    *(float2*)(dst + nt * 8) =
                        make_float2(c[mt][nt][rr * 2], c[mt][nt][rr * 2 + 1]);
            }
        }
}

// ---------------- combine (fp32, inline offsets) + g_cnt reset ----------------
__global__ __launch_bounds__(256) void combine_kernel(float* __restrict__ out)
{
    int idx = blockIdx.x * blockDim.x + threadIdx.x;
    int t = idx >> 8;
    int hq = (idx & 255) * 4;
    int v0 = g_pair[t * 2 + 0], v1 = g_pair[t * 2 + 1];
    int e0 = v0 >> 12, e1 = v1 >> 12;
    int off0 = 0, off1 = 0;
#pragma unroll
    for (int i = 0; i < NEXP; i++) {
        int ci = g_cnt[i];
        if (i < e0) off0 += ci;
        if (i < e1) off1 += ci;
    }
    int gi0 = off0 + (v0 & (MAXP - 1));
    int gi1 = off1 + (v1 & (MAXP - 1));
    float4 a = *(const float4*)(g_dout + (size_t)gi0 * HDIM + hq);
    float4 b = *(const float4*)(g_dout + (size_t)gi1 * HDIM + hq);
    float4 o = {a.x + b.x, a.y + b.y, a.z + b.z, a.w + b.w};
    *(float4*)(out + (size_t)t * HDIM + hq) = o;

    // last block re-zeroes g_cnt for the next replay
    __syncthreads();
    if (threadIdx.x == 0) {
        __threadfence();
        int d = atomicAdd(&g_cfin, 1);
        if (d == (int)gridDim.x - 1) {
            g_cfin = 0;
#pragma unroll
            for (int i = 0; i < NEXP; i++) g_cnt[i] = 0;
            __threadfence();
        }
    }
}

// ---------------- launch ----------------
extern "C" void kernel_launch(void* const* d_in, const int* in_sizes, int n_in,
                              void* d_out, int out_size)
{
    const float* x  = (const float*)d_in[0];
    const float* Wr = (const float*)d_in[1];
    const float* Wg = (const float*)d_in[2];
    const float* Wu = (const float*)d_in[3];
    const float* Wd = (const float*)d_in[4];
    float* out = (float*)d_out;

    cudaFuncSetAttribute(mg_gateup, cudaFuncAttributeMaxDynamicSharedMemorySize, GEMM_SMEM);
    cudaFuncSetAttribute(mg_down,   cudaFuncAttributeMaxDynamicSharedMemorySize, GEMM_SMEM);

    router_kernel<<<T_TOK / 16, 128>>>(x, Wr);

    dim3 gg(72, FDIM / 64);
    mg_gateup<<<gg, 256, GEMM_SMEM>>>(Wg, Wu);

    dim3 gd(72, HDIM / 128);
    mg_down<<<gd, 256, GEMM_SMEM>>>(Wd);

    combine_kernel<<<(T_TOK * HDIM / 4) / 256, 256>>>(out);
}

// round 17
// speedup vs baseline: 1.0510x; 1.0266x over previous
#include <cuda_runtime.h>
#include <cuda_fp16.h>
#include <math.h>
#include <stdint.h>

#define T_TOK 4096
#define HDIM 1024
#define FDIM 512
#define NEXP 8
#define MAXP 4096

// ---------------- device scratch ----------------
__device__ int    g_cnt[NEXP];          // zero at load; reset by combine each replay
__device__ int    g_tok[NEXP * MAXP];
__device__ float  g_wt [NEXP * MAXP];
__device__ int    g_pair[T_TOK * 2];
__device__ __half g_xh   [T_TOK * HDIM];
__device__ __half g_acth [T_TOK * 2 * FDIM];
__device__ __half g_douth[T_TOK * 2 * HDIM];
__device__ int    g_cfin;

#define MMA16(c, a0, a1, a2, a3, b0, b1) \
    asm volatile("mma.sync.aligned.m16n8k16.row.col.f32.f16.f16.f32 " \
        "{%0,%1,%2,%3},{%4,%5,%6,%7},{%8,%9},{%0,%1,%2,%3};" \
        : "+f"((c)[0]), "+f"((c)[1]), "+f"((c)[2]), "+f"((c)[3]) \
        : "r"(a0), "r"(a1), "r"(a2), "r"(a3), "r"(b0), "r"(b1))

__device__ __forceinline__ uint32_t h2u(__half2 h) {
    uint32_t u; asm("mov.b32 %0, %1;" : "=r"(u) : "r"(*(uint32_t*)&h)); return u;
}

// smem (uint2 units): A 8q x 132m, B 8q x 132n, per buffer 2112 uint2 (R7 layout)
#define QST 132
#define BUF2 2112
#define AOFF(b) ((b) * BUF2)
#define BOFF(b) ((b) * BUF2 + 8 * QST)
#define META2 (2 * BUF2)
#define GEMM_SMEM (2 * BUF2 * 8 + 1024)

__device__ __forceinline__ bool tile_map(int tile, int& e, int& m0, int& gbase, int& cnt) {
    int acc = 0, off = 0;
#pragma unroll
    for (int i = 0; i < NEXP; i++) {
        int c = g_cnt[i];
        int nt = (c + 127) >> 7;
        if (tile < acc + nt) { e = i; m0 = (tile - acc) << 7; gbase = off; cnt = c; return true; }
        acc += nt; off += c;
    }
    return false;
}

// ---------------- router v6: routing pass + coalesced fp16 convert pass ----------------
__global__ __launch_bounds__(128) void router_kernel(
    const float* __restrict__ x, const float* __restrict__ Wr)
{
    int lane = threadIdx.x & 31, wid = threadIdx.x >> 5;
    int tb = blockIdx.x * 16;
    int t0 = tb + wid * 4;
    const float* xr0 = x + (size_t)(t0 + 0) * HDIM;
    const float* xr1 = x + (size_t)(t0 + 1) * HDIM;
    const float* xr2 = x + (size_t)(t0 + 2) * HDIM;
    const float* xr3 = x + (size_t)(t0 + 3) * HDIM;

    float acc[4][NEXP];
#pragma unroll
    for (int i = 0; i < 4; i++)
#pragma unroll
        for (int e = 0; e < NEXP; e++) acc[i][e] = 0.0f;

    for (int h = lane; h < HDIM; h += 32) {
        const float4* wr4 = (const float4*)(Wr + (size_t)h * NEXP);
        float4 w0 = wr4[0], w1 = wr4[1];
        float xs[4] = {xr0[h], xr1[h], xr2[h], xr3[h]};
#pragma unroll
        for (int i = 0; i < 4; i++) {
            acc[i][0] = fmaf(xs[i], w0.x, acc[i][0]);
            acc[i][1] = fmaf(xs[i], w0.y, acc[i][1]);
            acc[i][2] = fmaf(xs[i], w0.z, acc[i][2]);
            acc[i][3] = fmaf(xs[i], w0.w, acc[i][3]);
            acc[i][4] = fmaf(xs[i], w1.x, acc[i][4]);
            acc[i][5] = fmaf(xs[i], w1.y, acc[i][5]);
            acc[i][6] = fmaf(xs[i], w1.z, acc[i][6]);
            acc[i][7] = fmaf(xs[i], w1.w, acc[i][7]);
        }
    }
#pragma unroll
    for (int i = 0; i < 4; i++)
#pragma unroll
        for (int e = 0; e < NEXP; e++)
#pragma unroll
            for (int o = 16; o > 0; o >>= 1)
                acc[i][e] += __shfl_xor_sync(0xFFFFFFFFu, acc[i][e], o);

    if (lane == 0) {
#pragma unroll
        for (int i = 0; i < 4; i++) {
            int t = t0 + i;
            float m = acc[i][0];
#pragma unroll
            for (int e = 1; e < NEXP; e++) m = fmaxf(m, acc[i][e]);
            float p[NEXP];
#pragma unroll
            for (int e = 0; e < NEXP; e++) p[e] = expf(acc[i][e] - m);
            int i0 = 0;
#pragma unroll
            for (int e = 1; e < NEXP; e++) if (p[e] > p[i0]) i0 = e;
            int i1 = (i0 == 0) ? 1 : 0;
#pragma unroll
            for (int e = 0; e < NEXP; e++) if (e != i0 && p[e] > p[i1]) i1 = e;
            float s = p[i0] + p[i1];
            int p0 = atomicAdd(&g_cnt[i0], 1);
            g_tok[i0 * MAXP + p0] = t; g_wt[i0 * MAXP + p0] = p[i0] / s;
            g_pair[t * 2 + 0] = (i0 << 12) | p0;
            int p1 = atomicAdd(&g_cnt[i1], 1);
            g_tok[i1 * MAXP + p1] = t; g_wt[i1 * MAXP + p1] = p[i1] / s;
            g_pair[t * 2 + 1] = (i1 << 12) | p1;
        }
    }

    // phase 2: coalesced x -> fp16 for this block's 16 tokens
    const float4* xs4 = (const float4*)(x + (size_t)tb * HDIM);
    uint2* xd = (uint2*)(g_xh + (size_t)tb * HDIM);
#pragma unroll
    for (int j = 0; j < 32; j++) {
        int idx = j * 128 + threadIdx.x;        // 4096 float4 = 16 rows
        float4 v = xs4[idx];
        __half2 lo = __floats2half2_rn(v.x, v.y);
        __half2 hi = __floats2half2_rn(v.z, v.w);
        xd[idx] = make_uint2(h2u(lo), h2u(hi));
    }
}

// =====================================================================
// gate+up fp16 GEMM + SwiGLU (R7 core, unchanged).
// =====================================================================
__global__ __launch_bounds__(256, 2) void mg_gateup(
    const float* __restrict__ Wg,
    const float* __restrict__ Wu)
{
    extern __shared__ uint2 sm2[];
    int e, m0, gbase, cnt;
    if (!tile_map(blockIdx.x, e, m0, gbase, cnt)) return;
    int f0 = blockIdx.y * 64;

    int tid = threadIdx.x, lane = tid & 31, wid = tid >> 5;
    int wmi = wid >> 2, wni = wid & 3;
    int lr = lane >> 2, l3 = lane & 3;

    int*   stok = (int*)(sm2 + META2);
    float* swt  = (float*)(sm2 + META2 + 64);
    if (tid < 128) {
        int r = m0 + tid, rc = min(r, cnt - 1);
        stok[tid] = g_tok[e * MAXP + rc];
        swt[tid]  = (r < cnt) ? g_wt[e * MAXP + rc] : 0.0f;
    }
    __syncthreads();

    int am = tid >> 1, kh = (tid & 1) * 16;
    const __half* arow = g_xh + (size_t)stok[am] * HDIM + kh;
    int aqb = (tid & 1) * 4;
    int bp = (wid & 3) + 8 * (wid >> 2);
    int n4 = lane * 4;
    int bmat = (n4 >> 4) & 1;
    int bf = ((n4 >> 5) << 4) + (((n4 >> 3) & 1) << 3) + (n4 & 7);
    const float* wsel = (bmat ? Wu : Wg) + (size_t)e * HDIM * FDIM + f0 + bf;

    uint4 au0, au1;
    float4 bv0, bv1, bv2, bv3;
    auto LOADG = [&](int s) {
        int kb = s * 32;
        const uint4* ap = (const uint4*)(arow + kb);
        au0 = ap[0]; au1 = ap[1];
        const float* bp0 = wsel + (size_t)(kb + 2 * bp) * FDIM;
        bv0 = *(const float4*)bp0;
        bv1 = *(const float4*)(bp0 + FDIM);
        bv2 = *(const float4*)(bp0 + 8 * FDIM);
        bv3 = *(const float4*)(bp0 + 9 * FDIM);
    };
    auto STORES = [&](int b) {
        uint2* A = sm2 + AOFF(b);
        uint2* B = sm2 + BOFF(b);
        const uint32_t* a0 = (const uint32_t*)&au0;
        const uint32_t* a1 = (const uint32_t*)&au1;
#pragma unroll
        for (int j = 0; j < 4; j++)
            A[(aqb + j) * QST + am] = make_uint2(a0[j], a1[j]);
        const float* v0 = (const float*)&bv0;
        const float* v1 = (const float*)&bv1;
        const float* v2 = (const float*)&bv2;
        const float* v3 = (const float*)&bv3;
#pragma unroll
        for (int j = 0; j < 4; j++) {
            uint32_t lo = h2u(__floats2half2_rn(v0[j], v1[j]));
            uint32_t hi = h2u(__floats2half2_rn(v2[j], v3[j]));
            B[wid * QST + n4 + j] = make_uint2(lo, hi);
        }
    };

    float c[4][4][4];
#pragma unroll
    for (int a = 0; a < 4; a++)
#pragma unroll
        for (int b = 0; b < 4; b++)
#pragma unroll
            for (int k = 0; k < 4; k++) c[a][b][k] = 0.0f;

    LOADG(0); STORES(0);
    const int NS = HDIM / 32;
    for (int s = 0; s < NS; s++) {
        __syncthreads();
        if (s + 1 < NS) LOADG(s + 1);
        uint2* A = sm2 + AOFF(s & 1);
        uint2* B = sm2 + BOFF(s & 1);
#pragma unroll
        for (int kk = 0; kk < 2; kk++) {
            int q = kk * 4 + l3;
            uint2 af[4], ah[4];
#pragma unroll
            for (int mt = 0; mt < 4; mt++) {
                int m = wmi * 64 + mt * 16 + lr;
                af[mt] = A[q * QST + m];
                ah[mt] = A[q * QST + m + 8];
            }
#pragma unroll
            for (int nt = 0; nt < 4; nt++) {
                uint2 b = B[q * QST + wni * 32 + nt * 8 + lr];
#pragma unroll
                for (int mt = 0; mt < 4; mt++)
                    MMA16(c[mt][nt], af[mt].x, ah[mt].x, af[mt].y, ah[mt].y, b.x, b.y);
            }
        }
        if (s + 1 < NS) STORES((s + 1) & 1);
    }

#pragma unroll
    for (int mt = 0; mt < 4; mt++)
#pragma unroll
        for (int rr = 0; rr < 2; rr++) {
            int row = wmi * 64 + mt * 16 + lr + rr * 8;
            if (m0 + row < cnt) {
                float w = swt[row];
                __half* dst = g_acth + (size_t)(gbase + m0 + row) * FDIM + f0 + wni * 16 + 2 * l3;
#pragma unroll
                for (int ntl = 0; ntl < 2; ntl++) {
                    float gv0 = c[mt][ntl][rr * 2],     gv1 = c[mt][ntl][rr * 2 + 1];
                    float uv0 = c[mt][ntl + 2][rr * 2], uv1 = c[mt][ntl + 2][rr * 2 + 1];
                    float o0 = w * (gv0 / (1.0f + expf(-gv0))) * uv0;
                    float o1 = w * (gv1 / (1.0f + expf(-gv1))) * uv1;
                    *(__half2*)(dst + ntl * 8) = __floats2half2_rn(o0, o1);
                }
            }
        }
}

// =====================================================================
// down fp16 GEMM (R7 core), fp16 output.
// =====================================================================
__global__ __launch_bounds__(256, 2) void mg_down(const float* __restrict__ Wd)
{
    extern __shared__ uint2 sm2[];
    int e, m0, gbase, cnt;
    if (!tile_map(blockIdx.x, e, m0, gbase, cnt)) return;
    int h0 = blockIdx.y * 128;

    int tid = threadIdx.x, lane = tid & 31, wid = tid >> 5;
    int wmi = wid >> 2, wni = wid & 3;
    int lr = lane >> 2, l3 = lane & 3;

    int am = tid >> 1, kh = (tid & 1) * 16;
    const __half* arow = g_acth + (size_t)(gbase + min(m0 + am, cnt - 1)) * FDIM + kh;
    int aqb = (tid & 1) * 4;
    int bp = (wid & 3) + 8 * (wid >> 2);
    int n4 = lane * 4;
    const float* wsel = Wd + (size_t)e * FDIM * HDIM + h0 + n4;

    uint4 au0, au1;
    float4 bv0, bv1, bv2, bv3;
    auto LOADG = [&](int s) {
        int kb = s * 32;
        const uint4* ap = (const uint4*)(arow + kb);
        au0 = ap[0]; au1 = ap[1];
        const float* bp0 = wsel + (size_t)(kb + 2 * bp) * HDIM;
        bv0 = *(const float4*)bp0;
        bv1 = *(const float4*)(bp0 + HDIM);
        bv2 = *(const float4*)(bp0 + 8 * HDIM);
        bv3 = *(const float4*)(bp0 + 9 * HDIM);
    };
    auto STORES = [&](int b) {
        uint2* A = sm2 + AOFF(b);
        uint2* B = sm2 + BOFF(b);
        const uint32_t* a0 = (const uint32_t*)&au0;
        const uint32_t* a1 = (const uint32_t*)&au1;
#pragma unroll
        for (int j = 0; j < 4; j++)
            A[(aqb + j) * QST + am] = make_uint2(a0[j], a1[j]);
        const float* v0 = (const float*)&bv0;
        const float* v1 = (const float*)&bv1;
        const float* v2 = (const float*)&bv2;
        const float* v3 = (const float*)&bv3;
#pragma unroll
        for (int j = 0; j < 4; j++) {
            uint32_t lo = h2u(__floats2half2_rn(v0[j], v1[j]));
            uint32_t hi = h2u(__floats2half2_rn(v2[j], v3[j]));
            B[wid * QST + n4 + j] = make_uint2(lo, hi);
        }
    };

    float c[4][4][4];
#pragma unroll
    for (int a = 0; a < 4; a++)
#pragma unroll
        for (int b = 0; b < 4; b++)
#pragma unroll
            for (int k = 0; k < 4; k++) c[a][b][k] = 0.0f;

    LOADG(0); STORES(0);
    const int NS = FDIM / 32;
    for (int s = 0; s < NS; s++) {
        __syncthreads();
        if (s + 1 < NS) LOADG(s + 1);
        uint2* A = sm2 + AOFF(s & 1);
        uint2* B = sm2 + BOFF(s & 1);
#pragma unroll
        for (int kk = 0; kk < 2; kk++) {
            int q = kk * 4 + l3;
            uint2 af[4], ah[4];
#pragma unroll
            for (int mt = 0; mt < 4; mt++) {
                int m = wmi * 64 + mt * 16 + lr;
                af[mt] = A[q * QST + m];
                ah[mt] = A[q * QST + m + 8];
            }
#pragma unroll
            for (int nt = 0; nt < 4; nt++) {
                uint2 b = B[q * QST + wni * 32 + nt * 8 + lr];
#pragma unroll
                for (int mt = 0; mt < 4; mt++)
                    MMA16(c[mt][nt], af[mt].x, ah[mt].x, af[mt].y, ah[mt].y, b.x, b.y);
            }
        }
        if (s + 1 < NS) STORES((s + 1) & 1);
    }

#pragma unroll
    for (int mt = 0; mt < 4; mt++)
#pragma unroll
        for (int rr = 0; rr < 2; rr++) {
            int row = wmi * 64 + mt * 16 + lr + rr * 8;
            if (m0 + row < cnt) {
                __half* dst = g_douth + (size_t)(gbase + m0 + row) * HDIM + h0 + wni * 32 + 2 * l3;
#pragma unroll
                for (int nt = 0; nt < 4; nt++)
                    *(__half2*)(dst + nt * 8) =
                        __floats2half2_rn(c[mt][nt][rr * 2], c[mt][nt][rr * 2 + 1]);
            }
        }
}

// ---------------- combine (fp16 sources, fp32 out) + g_cnt reset ----------------
__global__ __launch_bounds__(256) void combine_kernel(float* __restrict__ out)
{
    int idx = blockIdx.x * blockDim.x + threadIdx.x;
    int t = idx >> 8;
    int hq = (idx & 255) * 4;
    int v0 = g_pair[t * 2 + 0], v1 = g_pair[t * 2 + 1];
    int e0 = v0 >> 12, e1 = v1 >> 12;
    int off0 = 0, off1 = 0;
#pragma unroll
    for (int i = 0; i < NEXP; i++) {
        int ci = g_cnt[i];
        if (i < e0) off0 += ci;
        if (i < e1) off1 += ci;
    }
    size_t gi0 = (size_t)(off0 + (v0 & (MAXP - 1))) * HDIM + hq;
    size_t gi1 = (size_t)(off1 + (v1 & (MAXP - 1))) * HDIM + hq;
    uint2 ua = *(const uint2*)(g_douth + gi0);
    uint2 ub = *(const uint2*)(g_douth + gi1);
    float2 fa0 = __half22float2(*(__half2*)&ua.x), fa1 = __half22float2(*(__half2*)&ua.y);
    float2 fb0 = __half22float2(*(__half2*)&ub.x), fb1 = __half22float2(*(__half2*)&ub.y);
    float4 o = { fa0.x + fb0.x, fa0.y + fb0.y, fa1.x + fb1.x, fa1.y + fb1.y };
    *(float4*)(out + (size_t)t * HDIM + hq) = o;

    __syncthreads();
    if (threadIdx.x == 0) {
        __threadfence();
        int d = atomicAdd(&g_cfin, 1);
        if (d == (int)gridDim.x - 1) {
            g_cfin = 0;
#pragma unroll
            for (int i = 0; i < NEXP; i++) g_cnt[i] = 0;
            __threadfence();
        }
    }
}

// ---------------- launch ----------------
extern "C" void kernel_launch(void* const* d_in, const int* in_sizes, int n_in,
                              void* d_out, int out_size)
{
    const float* x  = (const float*)d_in[0];
    const float* Wr = (const float*)d_in[1];
    const float* Wg = (const float*)d_in[2];
    const float* Wu = (const float*)d_in[3];
    const float* Wd = (const float*)d_in[4];
    float* out = (float*)d_out;

    cudaFuncSetAttribute(mg_gateup, cudaFuncAttributeMaxDynamicSharedMemorySize, GEMM_SMEM);
    cudaFuncSetAttribute(mg_down,   cudaFuncAttributeMaxDynamicSharedMemorySize, GEMM_SMEM);

    router_kernel<<<T_TOK / 16, 128>>>(x, Wr);

    dim3 gg(72, FDIM / 64);
    mg_gateup<<<gg, 256, GEMM_SMEM>>>(Wg, Wu);

    dim3 gd(72, HDIM / 128);
    mg_down<<<gd, 256, GEMM_SMEM>>>(Wd);

    combine_kernel<<<(T_TOK * HDIM / 4) / 256, 256>>>(out);
}